// round 11
// baseline (speedup 1.0000x reference)
#include <cuda_runtime.h>
#include <math.h>

#define NROWS 8192
#define KIN   512
#define HD    256
#define WD    64
#define BK    8
#define BM    32      // rows per CTA
#define TM    4       // rows per thread (8 warps x 4 rows = 32)
#define TN    8       // cols per thread
#define BSW_STRIDE 66 // bank step 2 -> conflict-free u64 LDS

// ---------------------------------------------------------------------------
// f32x2 packed helpers (FFMA2: 2 MACs per instruction on sm_103a)
// ---------------------------------------------------------------------------
__device__ __forceinline__ unsigned long long pack_ff(float a) {
    unsigned long long r;
    unsigned int u = __float_as_uint(a);
    asm("mov.b64 %0, {%1, %1};" : "=l"(r) : "r"(u));
    return r;
}
__device__ __forceinline__ void ffma2(unsigned long long &c,
                                      unsigned long long a,
                                      unsigned long long b) {
    asm("fma.rn.f32x2 %0, %1, %2, %0;" : "+l"(c) : "l"(a), "l"(b));
}
__device__ __forceinline__ float2 unpack_ff(unsigned long long v) {
    unsigned int lo, hi;
    asm("mov.b64 {%0, %1}, %2;" : "=r"(lo), "=r"(hi) : "l"(v));
    float2 f;
    f.x = __uint_as_float(lo);
    f.y = __uint_as_float(hi);
    return f;
}

// ---------------------------------------------------------------------------
// Fully fused network: per CTA, 32 rows flow through all three layers.
//   h1 = relu(X@W1+b1)  -> smem
//   h2 = relu(h1@W2+b2) -> smem (overwrites h1)
//   out += sum( tanh(h2@Wq+bq) * Wh )   [mean neighbor weight == 1.0]
// 256 threads: tx = lane (32 col-blocks of 8), ty = warp (8 row-groups of 4).
// 2 CTAs/SM -> 16 warps/SM (4 per SMSP) for latency hiding.
// ---------------------------------------------------------------------------
__global__ void __launch_bounds__(256, 2) fused_net(
    const float* __restrict__ X,
    const float* __restrict__ W1, const float* __restrict__ b1,
    const float* __restrict__ W2, const float* __restrict__ b2,
    const float* __restrict__ Wq, const float* __restrict__ bq,
    const float* __restrict__ Wh, float* __restrict__ out)
{
    __shared__ __align__(16) float h1s[BM * HD];           // 32 KB activations
    __shared__ __align__(16) float BsW[32 * BSW_STRIDE];   // swizzled weight slab
    __shared__ __align__(16) float Bs3[BK * WD];           // stage-3 Wq slab
    __shared__ __align__(16) float As1[BM * BK];           // stage-1 X slab
    __shared__ float red[8];

    const int tid = threadIdx.x;
    const int tx  = tid & 31;
    const int ty  = tid >> 5;                  // 0..7
    const int rowBase = blockIdx.x * BM;

    // loader mappings
    const int aRow = tid >> 1;                 // 0..31 (tid<64 used)
    const int aK   = (tid & 1) * 4;
    const int lcol = (tid & 63) * 4;           // weight col
    const int cbS  = (lcol >> 3) * BSW_STRIDE + (lcol & 7);  // swizzled dest
    const int rowG = (tid >> 6) * 2;           // 0,2,4,6 (2 k-rows per thread)
    const int wRow = tid >> 4;                 // 0..7 (stage 3, tid<128)
    const int wCol = (tid & 15) * 4;

    unsigned long long acc[TM][TN / 2];

    // ======================= stage 1: h1 = relu(X@W1+b1), K=512 ============
    #pragma unroll
    for (int i = 0; i < TM; i++)
        #pragma unroll
        for (int j = 0; j < TN / 2; j++) acc[i][j] = 0ull;

    float4 pa;
    float4 pb[2];
    if (tid < 64)
        pa = *(const float4*)(X + (long)(rowBase + aRow) * KIN + aK);
    #pragma unroll
    for (int r = 0; r < 2; r++)
        pb[r] = *(const float4*)(W1 + (long)(rowG + r) * HD + lcol);

    for (int k0 = 0; k0 < KIN; k0 += BK) {
        if (tid < 64) *(float4*)&As1[aRow * BK + aK] = pa;
        #pragma unroll
        for (int r = 0; r < 2; r++) {
            *(float2*)&BsW[cbS + (rowG + r) * 8]     = make_float2(pb[r].x, pb[r].y);
            *(float2*)&BsW[cbS + (rowG + r) * 8 + 2] = make_float2(pb[r].z, pb[r].w);
        }
        __syncthreads();

        if (k0 + BK < KIN) {
            if (tid < 64)
                pa = *(const float4*)(X + (long)(rowBase + aRow) * KIN + k0 + BK + aK);
            #pragma unroll
            for (int r = 0; r < 2; r++)
                pb[r] = *(const float4*)(W1 + (long)(k0 + BK + rowG + r) * HD + lcol);
        }

        #pragma unroll
        for (int kp = 0; kp < BK / 2; kp++) {
            float2 ap[TM];
            #pragma unroll
            for (int i = 0; i < TM; i++)
                ap[i] = *(const float2*)&As1[(ty * TM + i) * BK + 2 * kp];
            #pragma unroll
            for (int q = 0; q < 2; q++) {
                const int kk = 2 * kp + q;
                unsigned long long b2[TN / 2];
                #pragma unroll
                for (int j = 0; j < TN / 2; j++)
                    b2[j] = *(const unsigned long long*)
                                &BsW[tx * BSW_STRIDE + kk * 8 + 2 * j];
                #pragma unroll
                for (int i = 0; i < TM; i++) {
                    unsigned long long a2 = pack_ff(q ? ap[i].y : ap[i].x);
                    #pragma unroll
                    for (int j = 0; j < TN / 2; j++) ffma2(acc[i][j], a2, b2[j]);
                }
            }
        }
        __syncthreads();
    }

    // prefetch first W2 slab (overlap with epilogue)
    #pragma unroll
    for (int r = 0; r < 2; r++)
        pb[r] = *(const float4*)(W2 + (long)(rowG + r) * HD + lcol);

    // epilogue 1 -> h1s
    {
        const int c = tx * 8;
        const float4 bva = *(const float4*)&b1[c];
        const float4 bvb = *(const float4*)&b1[c + 4];
        #pragma unroll
        for (int i = 0; i < TM; i++) {
            const int r = ty * TM + i;
            float2 v0 = unpack_ff(acc[i][0]);
            float2 v1 = unpack_ff(acc[i][1]);
            float2 v2 = unpack_ff(acc[i][2]);
            float2 v3 = unpack_ff(acc[i][3]);
            float4 o0 = make_float4(fmaxf(v0.x + bva.x, 0.f), fmaxf(v0.y + bva.y, 0.f),
                                    fmaxf(v1.x + bva.z, 0.f), fmaxf(v1.y + bva.w, 0.f));
            float4 o1 = make_float4(fmaxf(v2.x + bvb.x, 0.f), fmaxf(v2.y + bvb.y, 0.f),
                                    fmaxf(v3.x + bvb.z, 0.f), fmaxf(v3.y + bvb.w, 0.f));
            *(float4*)&h1s[r * HD + c]     = o0;
            *(float4*)&h1s[r * HD + c + 4] = o1;
        }
    }
    __syncthreads();

    // ======================= stage 2: h2 = relu(h1@W2+b2), K=256 ===========
    #pragma unroll
    for (int i = 0; i < TM; i++)
        #pragma unroll
        for (int j = 0; j < TN / 2; j++) acc[i][j] = 0ull;

    for (int k0 = 0; k0 < HD; k0 += BK) {
        #pragma unroll
        for (int r = 0; r < 2; r++) {
            *(float2*)&BsW[cbS + (rowG + r) * 8]     = make_float2(pb[r].x, pb[r].y);
            *(float2*)&BsW[cbS + (rowG + r) * 8 + 2] = make_float2(pb[r].z, pb[r].w);
        }
        __syncthreads();

        if (k0 + BK < HD) {
            #pragma unroll
            for (int r = 0; r < 2; r++)
                pb[r] = *(const float4*)(W2 + (long)(k0 + BK + rowG + r) * HD + lcol);
        }

        #pragma unroll
        for (int kp = 0; kp < BK / 2; kp++) {
            float2 ap[TM];
            #pragma unroll
            for (int i = 0; i < TM; i++)
                ap[i] = *(const float2*)&h1s[(ty * TM + i) * HD + k0 + 2 * kp];
            #pragma unroll
            for (int q = 0; q < 2; q++) {
                const int kk = 2 * kp + q;
                unsigned long long b2[TN / 2];
                #pragma unroll
                for (int j = 0; j < TN / 2; j++)
                    b2[j] = *(const unsigned long long*)
                                &BsW[tx * BSW_STRIDE + kk * 8 + 2 * j];
                #pragma unroll
                for (int i = 0; i < TM; i++) {
                    unsigned long long a2 = pack_ff(q ? ap[i].y : ap[i].x);
                    #pragma unroll
                    for (int j = 0; j < TN / 2; j++) ffma2(acc[i][j], a2, b2[j]);
                }
            }
        }
        __syncthreads();
    }

    // prefetch first Wq slab
    float4 pw;
    if (tid < 128)
        pw = *(const float4*)(Wq + (long)wRow * WD + wCol);

    // epilogue 2 -> h1s (all stage-2 reads are done: loop ended on a sync)
    {
        const int c = tx * 8;
        const float4 bva = *(const float4*)&b2[c];
        const float4 bvb = *(const float4*)&b2[c + 4];
        #pragma unroll
        for (int i = 0; i < TM; i++) {
            const int r = ty * TM + i;
            float2 v0 = unpack_ff(acc[i][0]);
            float2 v1 = unpack_ff(acc[i][1]);
            float2 v2 = unpack_ff(acc[i][2]);
            float2 v3 = unpack_ff(acc[i][3]);
            float4 o0 = make_float4(fmaxf(v0.x + bva.x, 0.f), fmaxf(v0.y + bva.y, 0.f),
                                    fmaxf(v1.x + bva.z, 0.f), fmaxf(v1.y + bva.w, 0.f));
            float4 o1 = make_float4(fmaxf(v2.x + bvb.x, 0.f), fmaxf(v2.y + bvb.y, 0.f),
                                    fmaxf(v3.x + bvb.z, 0.f), fmaxf(v3.y + bvb.w, 0.f));
            *(float4*)&h1s[r * HD + c]     = o0;
            *(float4*)&h1s[r * HD + c + 4] = o1;
        }
    }
    __syncthreads();

    // ======== stage 3: out += sum(tanh(h2@Wq+bq)*Wh), K=256, N=64 ==========
    unsigned long long acc3[TM];
    #pragma unroll
    for (int i = 0; i < TM; i++) acc3[i] = 0ull;

    for (int k0 = 0; k0 < HD; k0 += BK) {
        if (tid < 128) *(float4*)&Bs3[wRow * WD + wCol] = pw;
        __syncthreads();

        if (k0 + BK < HD && tid < 128)
            pw = *(const float4*)(Wq + (long)(k0 + BK + wRow) * WD + wCol);

        #pragma unroll
        for (int kp = 0; kp < BK / 2; kp++) {
            float2 ap[TM];
            #pragma unroll
            for (int i = 0; i < TM; i++)
                ap[i] = *(const float2*)&h1s[(ty * TM + i) * HD + k0 + 2 * kp];
            #pragma unroll
            for (int q = 0; q < 2; q++) {
                const int kk = 2 * kp + q;
                unsigned long long b2 =
                    *(const unsigned long long*)&Bs3[kk * WD + tx * 2];
                #pragma unroll
                for (int i = 0; i < TM; i++) {
                    unsigned long long a2 = pack_ff(q ? ap[i].y : ap[i].x);
                    ffma2(acc3[i], a2, b2);
                }
            }
        }
        __syncthreads();
    }

    // epilogue 3: tanh + dot Wh + block reduce + atomicAdd
    {
        const float2 bqv = *(const float2*)&bq[tx * 2];
        const float2 whv = *(const float2*)&Wh[tx * 2];
        float s = 0.f;
        #pragma unroll
        for (int i = 0; i < TM; i++) {
            float2 v = unpack_ff(acc3[i]);
            s += tanhf(v.x + bqv.x) * whv.x;
            s += tanhf(v.y + bqv.y) * whv.y;
        }
        #pragma unroll
        for (int o = 16; o > 0; o >>= 1)
            s += __shfl_down_sync(0xffffffffu, s, o);
        if (tx == 0) red[ty] = s;
        __syncthreads();
        if (tid == 0) {
            float t = 0.f;
            #pragma unroll
            for (int i = 0; i < 8; i++) t += red[i];
            atomicAdd(out, t);
        }
    }
}

__global__ void init_out(float* __restrict__ out, const float* __restrict__ bh)
{
    if (threadIdx.x == 0) out[0] = bh[0];
}

// ---------------------------------------------------------------------------
// kernel_launch
// inputs (metadata order): state_batch, W1, b1, W2, b2, Wq, bq, Wh, bh
// ---------------------------------------------------------------------------
extern "C" void kernel_launch(void* const* d_in, const int* in_sizes, int n_in,
                              void* d_out, int out_size)
{
    const float* X  = (const float*)d_in[0];
    const float* W1 = (const float*)d_in[1];
    const float* b1 = (const float*)d_in[2];
    const float* W2 = (const float*)d_in[3];
    const float* b2 = (const float*)d_in[4];
    const float* Wq = (const float*)d_in[5];
    const float* bq = (const float*)d_in[6];
    const float* Wh = (const float*)d_in[7];
    const float* bh = (const float*)d_in[8];
    float* out = (float*)d_out;

    // out = bh (also clears the 0xAA poison)
    init_out<<<1, 32>>>(out, bh);

    // whole network in one kernel: 256 CTAs x 256 threads, 32 rows each
    fused_net<<<NROWS / BM, 256>>>(X, W1, b1, W2, b2, Wq, bq, Wh, out);
}

// round 13
// speedup vs baseline: 1.2169x; 1.2169x over previous
#include <cuda_runtime.h>
#include <math.h>

#define NROWS 8192
#define KIN   512
#define HD    256
#define WD    64
#define BK    8
#define BM    32      // rows per CTA
#define TM    8       // rows per thread
#define TN    8       // cols per thread
#define BSW_STRIDE 68 // 272B row pitch: 16B-aligned, LDS.128 conflict-free

// ---------------------------------------------------------------------------
// f32x2 packed helpers (FFMA2: 2 MACs per instruction on sm_103a)
// ---------------------------------------------------------------------------
__device__ __forceinline__ unsigned long long pack_ff(float a) {
    unsigned long long r;
    unsigned int u = __float_as_uint(a);
    asm("mov.b64 %0, {%1, %1};" : "=l"(r) : "r"(u));
    return r;
}
__device__ __forceinline__ void ffma2(unsigned long long &c,
                                      unsigned long long a,
                                      unsigned long long b) {
    asm("fma.rn.f32x2 %0, %1, %2, %0;" : "+l"(c) : "l"(a), "l"(b));
}
__device__ __forceinline__ float2 unpack_ff(unsigned long long v) {
    unsigned int lo, hi;
    asm("mov.b64 {%0, %1}, %2;" : "=r"(lo), "=r"(hi) : "l"(v));
    float2 f;
    f.x = __uint_as_float(lo);
    f.y = __uint_as_float(hi);
    return f;
}

// ---------------------------------------------------------------------------
// Fully fused network: per CTA, 32 rows flow through all three layers.
//   h1 = relu(X@W1+b1)  -> smem
//   h2 = relu(h1@W2+b2) -> smem (overwrites h1)
//   out += sum( tanh(h2@Wq+bq) * Wh )   [mean neighbor weight == 1.0]
// 128 threads: tx = lane (32 col-blocks of 8), ty = warp (4 row-groups of 8).
// Double-buffered weight/A slabs: ONE __syncthreads per 8-kk slab; B
// fragments read as ulonglong2 (LDS.128, conflict-free at 272B pitch).
// ---------------------------------------------------------------------------
__global__ void __launch_bounds__(128, 2) fused_net(
    const float* __restrict__ X,
    const float* __restrict__ W1, const float* __restrict__ b1,
    const float* __restrict__ W2, const float* __restrict__ b2,
    const float* __restrict__ Wq, const float* __restrict__ bq,
    const float* __restrict__ Wh, float* __restrict__ out)
{
    __shared__ __align__(16) float h1s[BM * HD];              // 32 KB
    __shared__ __align__(16) float BsW[2][32 * BSW_STRIDE];   // 17.4 KB
    __shared__ __align__(16) float As1[2][BM * BK];           // 2 KB
    __shared__ __align__(16) float Bs3[BK * WD];              // 2 KB
    __shared__ float red[4];

    const int tid = threadIdx.x;
    const int tx  = tid & 31;
    const int ty  = tid >> 5;                  // 0..3
    const int rowBase = blockIdx.x * BM;

    // loader mappings
    const int aRow = tid >> 1;                 // 0..63 (tid<64 used)
    const int aK   = (tid & 1) * 4;
    const int lcol = (tid & 63) * 4;           // weight col
    const int cbS  = (lcol >> 3) * BSW_STRIDE + (lcol & 7);  // swizzled dest
    const int rowG = (tid >> 6) * 4;           // 0 or 4
    const int wRow = tid >> 4;                 // 0..7 (stage 3)
    const int wCol = (tid & 15) * 4;

    unsigned long long acc[TM][TN / 2];

    // ======================= stage 1: h1 = relu(X@W1+b1), K=512 ============
    #pragma unroll
    for (int i = 0; i < TM; i++)
        #pragma unroll
        for (int j = 0; j < TN / 2; j++) acc[i][j] = 0ull;

    float4 pa;
    float4 pb[4];

    // stage slab 0
    if (tid < 64) {
        pa = *(const float4*)(X + (long)(rowBase + aRow) * KIN + aK);
        *(float4*)&As1[0][aRow * BK + aK] = pa;
    }
    #pragma unroll
    for (int r = 0; r < 4; r++) {
        pb[r] = *(const float4*)(W1 + (long)(rowG + r) * HD + lcol);
        *(float4*)&BsW[0][cbS + (rowG + r) * 8] = pb[r];
    }
    __syncthreads();

    {
        int p = 0;
        for (int k0 = 0; k0 < KIN; k0 += BK, p ^= 1) {
            const bool more = (k0 + BK < KIN);
            if (more) {
                if (tid < 64)
                    pa = *(const float4*)(X + (long)(rowBase + aRow) * KIN + k0 + BK + aK);
                #pragma unroll
                for (int r = 0; r < 4; r++)
                    pb[r] = *(const float4*)(W1 + (long)(k0 + BK + rowG + r) * HD + lcol);
            }

            #pragma unroll
            for (int kp = 0; kp < BK / 2; kp++) {
                float2 ap[TM];
                #pragma unroll
                for (int i = 0; i < TM; i++)
                    ap[i] = *(const float2*)&As1[p][(ty * TM + i) * BK + 2 * kp];
                #pragma unroll
                for (int q = 0; q < 2; q++) {
                    const int kk = 2 * kp + q;
                    const ulonglong2 bA = *(const ulonglong2*)
                        &BsW[p][tx * BSW_STRIDE + kk * 8];
                    const ulonglong2 bB = *(const ulonglong2*)
                        &BsW[p][tx * BSW_STRIDE + kk * 8 + 4];
                    #pragma unroll
                    for (int i = 0; i < TM; i++) {
                        unsigned long long a2 = pack_ff(q ? ap[i].y : ap[i].x);
                        ffma2(acc[i][0], a2, bA.x);
                        ffma2(acc[i][1], a2, bA.y);
                        ffma2(acc[i][2], a2, bB.x);
                        ffma2(acc[i][3], a2, bB.y);
                    }
                }
            }

            if (more) {
                if (tid < 64) *(float4*)&As1[p ^ 1][aRow * BK + aK] = pa;
                #pragma unroll
                for (int r = 0; r < 4; r++)
                    *(float4*)&BsW[p ^ 1][cbS + (rowG + r) * 8] = pb[r];
            }
            __syncthreads();
        }
    }

    // prefetch W2 slab 0 (LDG latency covered by epilogue)
    #pragma unroll
    for (int r = 0; r < 4; r++)
        pb[r] = *(const float4*)(W2 + (long)(rowG + r) * HD + lcol);

    // epilogue 1 -> h1s
    {
        const int c = tx * 8;
        const float4 bva = *(const float4*)&b1[c];
        const float4 bvb = *(const float4*)&b1[c + 4];
        #pragma unroll
        for (int i = 0; i < TM; i++) {
            const int r = ty * TM + i;
            float2 v0 = unpack_ff(acc[i][0]);
            float2 v1 = unpack_ff(acc[i][1]);
            float2 v2 = unpack_ff(acc[i][2]);
            float2 v3 = unpack_ff(acc[i][3]);
            float4 o0 = make_float4(fmaxf(v0.x + bva.x, 0.f), fmaxf(v0.y + bva.y, 0.f),
                                    fmaxf(v1.x + bva.z, 0.f), fmaxf(v1.y + bva.w, 0.f));
            float4 o1 = make_float4(fmaxf(v2.x + bvb.x, 0.f), fmaxf(v2.y + bvb.y, 0.f),
                                    fmaxf(v3.x + bvb.z, 0.f), fmaxf(v3.y + bvb.w, 0.f));
            *(float4*)&h1s[r * HD + c]     = o0;
            *(float4*)&h1s[r * HD + c + 4] = o1;
        }
    }
    // stage W2 slab 0 (buffer 0 is idle: last stage-1 read was buffer 1)
    #pragma unroll
    for (int r = 0; r < 4; r++)
        *(float4*)&BsW[0][cbS + (rowG + r) * 8] = pb[r];
    __syncthreads();

    // ======================= stage 2: h2 = relu(h1@W2+b2), K=256 ===========
    #pragma unroll
    for (int i = 0; i < TM; i++)
        #pragma unroll
        for (int j = 0; j < TN / 2; j++) acc[i][j] = 0ull;

    {
        int p = 0;
        for (int k0 = 0; k0 < HD; k0 += BK, p ^= 1) {
            const bool more = (k0 + BK < HD);
            if (more) {
                #pragma unroll
                for (int r = 0; r < 4; r++)
                    pb[r] = *(const float4*)(W2 + (long)(k0 + BK + rowG + r) * HD + lcol);
            }

            #pragma unroll
            for (int kp = 0; kp < BK / 2; kp++) {
                float2 ap[TM];
                #pragma unroll
                for (int i = 0; i < TM; i++)
                    ap[i] = *(const float2*)&h1s[(ty * TM + i) * HD + k0 + 2 * kp];
                #pragma unroll
                for (int q = 0; q < 2; q++) {
                    const int kk = 2 * kp + q;
                    const ulonglong2 bA = *(const ulonglong2*)
                        &BsW[p][tx * BSW_STRIDE + kk * 8];
                    const ulonglong2 bB = *(const ulonglong2*)
                        &BsW[p][tx * BSW_STRIDE + kk * 8 + 4];
                    #pragma unroll
                    for (int i = 0; i < TM; i++) {
                        unsigned long long a2 = pack_ff(q ? ap[i].y : ap[i].x);
                        ffma2(acc[i][0], a2, bA.x);
                        ffma2(acc[i][1], a2, bA.y);
                        ffma2(acc[i][2], a2, bB.x);
                        ffma2(acc[i][3], a2, bB.y);
                    }
                }
            }

            if (more) {
                #pragma unroll
                for (int r = 0; r < 4; r++)
                    *(float4*)&BsW[p ^ 1][cbS + (rowG + r) * 8] = pb[r];
            }
            __syncthreads();
        }
    }

    // prefetch first Wq slab
    float4 pw = *(const float4*)(Wq + (long)wRow * WD + wCol);

    // epilogue 2 -> h1s (all stage-2 reads done: loop ended on a sync)
    {
        const int c = tx * 8;
        const float4 bva = *(const float4*)&b2[c];
        const float4 bvb = *(const float4*)&b2[c + 4];
        #pragma unroll
        for (int i = 0; i < TM; i++) {
            const int r = ty * TM + i;
            float2 v0 = unpack_ff(acc[i][0]);
            float2 v1 = unpack_ff(acc[i][1]);
            float2 v2 = unpack_ff(acc[i][2]);
            float2 v3 = unpack_ff(acc[i][3]);
            float4 o0 = make_float4(fmaxf(v0.x + bva.x, 0.f), fmaxf(v0.y + bva.y, 0.f),
                                    fmaxf(v1.x + bva.z, 0.f), fmaxf(v1.y + bva.w, 0.f));
            float4 o1 = make_float4(fmaxf(v2.x + bvb.x, 0.f), fmaxf(v2.y + bvb.y, 0.f),
                                    fmaxf(v3.x + bvb.z, 0.f), fmaxf(v3.y + bvb.w, 0.f));
            *(float4*)&h1s[r * HD + c]     = o0;
            *(float4*)&h1s[r * HD + c + 4] = o1;
        }
    }
    __syncthreads();

    // ======== stage 3: out += sum(tanh(h2@Wq+bq)*Wh), K=256, N=64 ==========
    unsigned long long acc3[TM];
    #pragma unroll
    for (int i = 0; i < TM; i++) acc3[i] = 0ull;

    for (int k0 = 0; k0 < HD; k0 += BK) {
        *(float4*)&Bs3[wRow * WD + wCol] = pw;
        __syncthreads();

        if (k0 + BK < HD)
            pw = *(const float4*)(Wq + (long)(k0 + BK + wRow) * WD + wCol);

        #pragma unroll
        for (int kp = 0; kp < BK / 2; kp++) {
            float2 ap[TM];
            #pragma unroll
            for (int i = 0; i < TM; i++)
                ap[i] = *(const float2*)&h1s[(ty * TM + i) * HD + k0 + 2 * kp];
            #pragma unroll
            for (int q = 0; q < 2; q++) {
                const int kk = 2 * kp + q;
                unsigned long long b2 =
                    *(const unsigned long long*)&Bs3[kk * WD + tx * 2];
                #pragma unroll
                for (int i = 0; i < TM; i++) {
                    unsigned long long a2 = pack_ff(q ? ap[i].y : ap[i].x);
                    ffma2(acc3[i], a2, b2);
                }
            }
        }
        __syncthreads();
    }

    // epilogue 3: tanh + dot Wh + block reduce + atomicAdd
    {
        const float2 bqv = *(const float2*)&bq[tx * 2];
        const float2 whv = *(const float2*)&Wh[tx * 2];
        float s = 0.f;
        #pragma unroll
        for (int i = 0; i < TM; i++) {
            float2 v = unpack_ff(acc3[i]);
            s += tanhf(v.x + bqv.x) * whv.x;
            s += tanhf(v.y + bqv.y) * whv.y;
        }
        #pragma unroll
        for (int o = 16; o > 0; o >>= 1)
            s += __shfl_down_sync(0xffffffffu, s, o);
        if (tx == 0) red[ty] = s;
        __syncthreads();
        if (tid == 0)
            atomicAdd(out, red[0] + red[1] + red[2] + red[3]);
    }
}

__global__ void init_out(float* __restrict__ out, const float* __restrict__ bh)
{
    if (threadIdx.x == 0) out[0] = bh[0];
}

// ---------------------------------------------------------------------------
// kernel_launch
// inputs (metadata order): state_batch, W1, b1, W2, b2, Wq, bq, Wh, bh
// ---------------------------------------------------------------------------
extern "C" void kernel_launch(void* const* d_in, const int* in_sizes, int n_in,
                              void* d_out, int out_size)
{
    const float* X  = (const float*)d_in[0];
    const float* W1 = (const float*)d_in[1];
    const float* b1 = (const float*)d_in[2];
    const float* W2 = (const float*)d_in[3];
    const float* b2 = (const float*)d_in[4];
    const float* Wq = (const float*)d_in[5];
    const float* bq = (const float*)d_in[6];
    const float* Wh = (const float*)d_in[7];
    const float* bh = (const float*)d_in[8];
    float* out = (float*)d_out;

    // out = bh (also clears the 0xAA poison)
    init_out<<<1, 32>>>(out, bh);

    // whole network in one kernel: 256 CTAs x 128 threads, 32 rows each
    fused_net<<<NROWS / BM, 128>>>(X, W1, b1, W2, b2, Wq, bq, Wh, out);
}

// round 16
// speedup vs baseline: 1.7743x; 1.4581x over previous
#include <cuda_runtime.h>
#include <cuda_bf16.h>
#include <math.h>
#include <stdint.h>

#define NROWS 8192
#define F_IN  512
#define HD    256
#define WD    64

// ---------------------------------------------------------------------------
// Scratch (device globals: allocation-free per harness rules)
// ---------------------------------------------------------------------------
static __device__ __nv_bfloat16 g_xh[NROWS * F_IN], g_xl[NROWS * F_IN];
static __device__ __nv_bfloat16 g_w1h[HD * F_IN],  g_w1l[HD * F_IN];   // [256,512]
static __device__ __nv_bfloat16 g_w2h[HD * HD],    g_w2l[HD * HD];     // [256,256]
static __device__ __nv_bfloat16 g_wqh[WD * HD],    g_wql[WD * HD];     // [64,256]
static __device__ __nv_bfloat16 g_h1h[NROWS * HD], g_h1l[NROWS * HD];
static __device__ __nv_bfloat16 g_h2h[NROWS * HD], g_h2l[NROWS * HD];

// ---------------------------------------------------------------------------
// helpers
// ---------------------------------------------------------------------------
__device__ __forceinline__ uint32_t smem_u32(const void* p) {
    uint32_t a;
    asm("{ .reg .u64 t; cvta.to.shared.u64 t, %1; cvt.u32.u64 %0, t; }"
        : "=r"(a) : "l"(p));
    return a;
}
__device__ __forceinline__ uint32_t pack_bf(__nv_bfloat16 a, __nv_bfloat16 b) {
    return (uint32_t)__bfloat16_as_ushort(a) |
           ((uint32_t)__bfloat16_as_ushort(b) << 16);
}
__device__ __forceinline__ void ldsm4(uint32_t r[4], uint32_t addr) {
    asm volatile("ldmatrix.sync.aligned.m8n8.x4.shared.b16 {%0,%1,%2,%3}, [%4];"
        : "=r"(r[0]), "=r"(r[1]), "=r"(r[2]), "=r"(r[3]) : "r"(addr));
}
__device__ __forceinline__ void mma16816(float c[4], const uint32_t a[4],
                                         uint32_t b0, uint32_t b1) {
    asm volatile(
        "mma.sync.aligned.m16n8k16.row.col.f32.bf16.bf16.f32 "
        "{%0,%1,%2,%3}, {%4,%5,%6,%7}, {%8,%9}, {%0,%1,%2,%3};"
        : "+f"(c[0]), "+f"(c[1]), "+f"(c[2]), "+f"(c[3])
        : "r"(a[0]), "r"(a[1]), "r"(a[2]), "r"(a[3]), "r"(b0), "r"(b1));
}
#define CP16(dst, src) \
    asm volatile("cp.async.cg.shared.global [%0], [%1], 16;" \
                 :: "r"(dst), "l"(src) : "memory")
#define CP_COMMIT() asm volatile("cp.async.commit_group;" ::: "memory")

// ---------------------------------------------------------------------------
// fp32 -> bf16 hi/lo split of X  (one float4 per thread)
// ---------------------------------------------------------------------------
__global__ void convert_X(const float* __restrict__ X,
                          __nv_bfloat16* __restrict__ Xh,
                          __nv_bfloat16* __restrict__ Xl)
{
    const long i = ((long)blockIdx.x * 256 + threadIdx.x) * 4;
    float4 v = *(const float4*)(X + i);
    __nv_bfloat16 h0 = __float2bfloat16(v.x), h1 = __float2bfloat16(v.y);
    __nv_bfloat16 h2 = __float2bfloat16(v.z), h3 = __float2bfloat16(v.w);
    *(uint2*)(Xh + i) = make_uint2(pack_bf(h0, h1), pack_bf(h2, h3));
    *(uint2*)(Xl + i) = make_uint2(
        pack_bf(__float2bfloat16(v.x - __bfloat162float(h0)),
                __float2bfloat16(v.y - __bfloat162float(h1))),
        pack_bf(__float2bfloat16(v.z - __bfloat162float(h2)),
                __float2bfloat16(v.w - __bfloat162float(h3))));
}

// ---------------------------------------------------------------------------
// Weight prep: W [K,N] f32 -> Wt_hi/Wt_lo [N,K] bf16 (transpose + split)
// ---------------------------------------------------------------------------
__global__ void convert_weights(
    const float* __restrict__ W1, const float* __restrict__ W2,
    const float* __restrict__ Wq,
    __nv_bfloat16* __restrict__ w1h, __nv_bfloat16* __restrict__ w1l,
    __nv_bfloat16* __restrict__ w2h, __nv_bfloat16* __restrict__ w2l,
    __nv_bfloat16* __restrict__ wqh, __nv_bfloat16* __restrict__ wql)
{
    const int idx = blockIdx.x * 256 + threadIdx.x;
    if (idx < F_IN * HD) {                 // W1 [512,256]
        int k = idx / HD, n = idx % HD;
        float v = W1[idx];
        __nv_bfloat16 h = __float2bfloat16(v);
        w1h[n * F_IN + k] = h;
        w1l[n * F_IN + k] = __float2bfloat16(v - __bfloat162float(h));
    }
    if (idx < HD * HD) {                   // W2 [256,256]
        int k = idx / HD, n = idx % HD;
        float v = W2[idx];
        __nv_bfloat16 h = __float2bfloat16(v);
        w2h[n * HD + k] = h;
        w2l[n * HD + k] = __float2bfloat16(v - __bfloat162float(h));
    }
    if (idx < HD * WD) {                   // Wq [256,64]
        int k = idx / WD, n = idx % WD;
        float v = Wq[idx];
        __nv_bfloat16 h = __float2bfloat16(v);
        wqh[n * HD + k] = h;
        wql[n * HD + k] = __float2bfloat16(v - __bfloat162float(h));
    }
}

// ---------------------------------------------------------------------------
// Split-bf16 tensor-core GEMM stage (mma.sync m16n8k16, fp32 accumulate):
//   C[8192, NDIM] = act(A @ B^T + bias),  A [8192,KDIM] hi/lo, B [NDIM,KDIM] hi/lo
//   ACT 0: relu -> split bf16 hi/lo store (feeds next stage)
//   ACT 1: out += sum(tanh(. + bias) * Wh)   [mean neighbor weight == 1.0]
// CTA: 256 thr (8 warps, 2x4), BM=64, BN=NDIM; grid 128. K chunks of 32,
// cp.async double-buffered smem (pitch 40 bf16: 16B-aligned, LDSM conflict-free).
// ---------------------------------------------------------------------------
template<int KDIM, int NDIM, int ACT>
__global__ void __launch_bounds__(256, 1) mma_stage(
    const __nv_bfloat16* __restrict__ Ahi, const __nv_bfloat16* __restrict__ Alo,
    const __nv_bfloat16* __restrict__ Bhi, const __nv_bfloat16* __restrict__ Blo,
    const float* __restrict__ bias,
    __nv_bfloat16* __restrict__ Chi, __nv_bfloat16* __restrict__ Clo,
    const float* __restrict__ Wh, float* __restrict__ out)
{
    extern __shared__ char dsm[];
    __shared__ float red[8];

    constexpr int NCH   = KDIM / 32;         // k-chunks
    constexpr int NW    = NDIM / 4;          // cols per warp
    constexpr int NT    = NW / 8;            // n-tiles per warp
    constexpr int NPAIR = NT / 2;
    constexpr int OFF_AL = 64 * 40 * 2;                  // 5120
    constexpr int OFF_BH = 2 * OFF_AL;                   // 10240
    constexpr int OFF_BL = OFF_BH + NDIM * 40 * 2;
    constexpr int SBUF   = OFF_BH + 2 * (NDIM * 40 * 2); // bytes per buffer

    const uint32_t sb = smem_u32(dsm);
    const int tid = threadIdx.x;
    const int wid = tid >> 5;
    const int lid = tid & 31;
    const int wm  = wid >> 2;                // 0..1
    const int wn  = wid & 3;                 // 0..3
    const long rowBase = (long)blockIdx.x * 64;

    // cp.async loader mapping (per chunk): 16B per op
    const int lr = tid >> 2;                 // 0..63
    const int lc = (tid & 3) * 8;            // 0,8,16,24 (bf16 elems)

    auto load_chunk = [&](int k0, uint32_t buf) {
        CP16(buf + (lr * 40 + lc) * 2,
             Ahi + (rowBase + lr) * KDIM + k0 + lc);
        CP16(buf + OFF_AL + (lr * 40 + lc) * 2,
             Alo + (rowBase + lr) * KDIM + k0 + lc);
        #pragma unroll
        for (int i = 0; i < NDIM / 64; i++) {
            const int n = i * 64 + lr;
            CP16(buf + OFF_BH + (n * 40 + lc) * 2,
                 Bhi + (long)n * KDIM + k0 + lc);
            CP16(buf + OFF_BL + (n * 40 + lc) * 2,
                 Blo + (long)n * KDIM + k0 + lc);
        }
    };

    // ldmatrix lane offsets (element units)
    const int aRowOff = ((lid >> 3) & 1) * 8 + (lid & 7);
    const int aColOff = ((lid >> 4) & 1) * 8;
    const int bRowOff = ((lid >> 4) & 1) * 8 + (lid & 7);
    const int bColOff = ((lid >> 3) & 1) * 8;

    float acc[2][NT][4];
    #pragma unroll
    for (int mi = 0; mi < 2; mi++)
        #pragma unroll
        for (int ni = 0; ni < NT; ni++)
            #pragma unroll
            for (int q = 0; q < 4; q++) acc[mi][ni][q] = 0.f;

    load_chunk(0, sb);
    CP_COMMIT();

    for (int ch = 0; ch < NCH; ch++) {
        const uint32_t cur = sb + (uint32_t)(ch & 1) * SBUF;
        if (ch + 1 < NCH) {
            load_chunk((ch + 1) * 32, sb + (uint32_t)((ch + 1) & 1) * SBUF);
            CP_COMMIT();
            asm volatile("cp.async.wait_group 1;" ::: "memory");
        } else {
            asm volatile("cp.async.wait_group 0;" ::: "memory");
        }
        __syncthreads();

        #pragma unroll
        for (int ks = 0; ks < 2; ks++) {
            const int kk = ks * 16;
            uint32_t ah[2][4], al[2][4];
            #pragma unroll
            for (int mi = 0; mi < 2; mi++) {
                const uint32_t ra = cur +
                    ((wm * 32 + mi * 16 + aRowOff) * 40 + kk + aColOff) * 2;
                ldsm4(ah[mi], ra);
                ldsm4(al[mi], ra + OFF_AL);
            }
            #pragma unroll
            for (int pr = 0; pr < NPAIR; pr++) {
                uint32_t bh[4], bl[4];
                const uint32_t rb = cur + OFF_BH +
                    ((wn * NW + pr * 16 + bRowOff) * 40 + kk + bColOff) * 2;
                ldsm4(bh, rb);
                ldsm4(bl, rb + (OFF_BL - OFF_BH));
                #pragma unroll
                for (int mi = 0; mi < 2; mi++) {
                    #pragma unroll
                    for (int t = 0; t < 2; t++) {
                        float* c = acc[mi][pr * 2 + t];
                        mma16816(c, ah[mi], bh[2 * t], bh[2 * t + 1]);
                        mma16816(c, ah[mi], bl[2 * t], bl[2 * t + 1]);
                        mma16816(c, al[mi], bh[2 * t], bh[2 * t + 1]);
                    }
                }
            }
        }
        __syncthreads();
    }

    if (ACT == 0) {
        // relu + bias, split to bf16 hi/lo, store pairs
        #pragma unroll
        for (int mi = 0; mi < 2; mi++) {
            const long r0 = rowBase + wm * 32 + mi * 16 + (lid >> 2);
            #pragma unroll
            for (int ni = 0; ni < NT; ni++) {
                const int col = wn * NW + ni * 8 + (lid & 3) * 2;
                const float b0 = bias[col], b1 = bias[col + 1];
                float f0 = fmaxf(acc[mi][ni][0] + b0, 0.f);
                float f1 = fmaxf(acc[mi][ni][1] + b1, 0.f);
                float f2 = fmaxf(acc[mi][ni][2] + b0, 0.f);
                float f3 = fmaxf(acc[mi][ni][3] + b1, 0.f);
                __nv_bfloat16 h0 = __float2bfloat16(f0), h1 = __float2bfloat16(f1);
                __nv_bfloat16 h2 = __float2bfloat16(f2), h3 = __float2bfloat16(f3);
                *(uint32_t*)(Chi + r0 * NDIM + col) = pack_bf(h0, h1);
                *(uint32_t*)(Clo + r0 * NDIM + col) =
                    pack_bf(__float2bfloat16(f0 - __bfloat162float(h0)),
                            __float2bfloat16(f1 - __bfloat162float(h1)));
                *(uint32_t*)(Chi + (r0 + 8) * NDIM + col) = pack_bf(h2, h3);
                *(uint32_t*)(Clo + (r0 + 8) * NDIM + col) =
                    pack_bf(__float2bfloat16(f2 - __bfloat162float(h2)),
                            __float2bfloat16(f3 - __bfloat162float(h3)));
            }
        }
    } else {
        float s = 0.f;
        #pragma unroll
        for (int mi = 0; mi < 2; mi++)
            #pragma unroll
            for (int ni = 0; ni < NT; ni++) {
                const int col = wn * NW + ni * 8 + (lid & 3) * 2;
                s += tanhf(acc[mi][ni][0] + bias[col])     * Wh[col];
                s += tanhf(acc[mi][ni][1] + bias[col + 1]) * Wh[col + 1];
                s += tanhf(acc[mi][ni][2] + bias[col])     * Wh[col];
                s += tanhf(acc[mi][ni][3] + bias[col + 1]) * Wh[col + 1];
            }
        #pragma unroll
        for (int o = 16; o > 0; o >>= 1)
            s += __shfl_down_sync(0xffffffffu, s, o);
        if (lid == 0) red[wid] = s;
        __syncthreads();
        if (tid == 0) {
            float t = 0.f;
            #pragma unroll
            for (int i = 0; i < 8; i++) t += red[i];
            atomicAdd(out, t);
        }
    }
}

__global__ void init_out(float* __restrict__ out, const float* __restrict__ bh)
{
    if (threadIdx.x == 0) out[0] = bh[0];
}

// ---------------------------------------------------------------------------
// kernel_launch
// inputs (metadata order): state_batch, W1, b1, W2, b2, Wq, bq, Wh, bh
// ---------------------------------------------------------------------------
extern "C" void kernel_launch(void* const* d_in, const int* in_sizes, int n_in,
                              void* d_out, int out_size)
{
    const float* X  = (const float*)d_in[0];
    const float* W1 = (const float*)d_in[1];
    const float* b1 = (const float*)d_in[2];
    const float* W2 = (const float*)d_in[3];
    const float* b2 = (const float*)d_in[4];
    const float* Wq = (const float*)d_in[5];
    const float* bq = (const float*)d_in[6];
    const float* Wh = (const float*)d_in[7];
    const float* bh = (const float*)d_in[8];
    float* out = (float*)d_out;

    __nv_bfloat16 *xh, *xl, *w1h, *w1l, *w2h, *w2l, *wqh, *wql;
    __nv_bfloat16 *h1h, *h1l, *h2h, *h2l;
    cudaGetSymbolAddress((void**)&xh,  g_xh);
    cudaGetSymbolAddress((void**)&xl,  g_xl);
    cudaGetSymbolAddress((void**)&w1h, g_w1h);
    cudaGetSymbolAddress((void**)&w1l, g_w1l);
    cudaGetSymbolAddress((void**)&w2h, g_w2h);
    cudaGetSymbolAddress((void**)&w2l, g_w2l);
    cudaGetSymbolAddress((void**)&wqh, g_wqh);
    cudaGetSymbolAddress((void**)&wql, g_wql);
    cudaGetSymbolAddress((void**)&h1h, g_h1h);
    cudaGetSymbolAddress((void**)&h1l, g_h1l);
    cudaGetSymbolAddress((void**)&h2h, g_h2h);
    cudaGetSymbolAddress((void**)&h2l, g_h2l);

    // dynamic smem: 2 buffers of (A 10240 + B NDIM*160) bytes
    const int SM12 = 2 * (10240 + HD * 160);   // 102400
    const int SM3  = 2 * (10240 + WD * 160);   // 40960
    cudaFuncSetAttribute((const void*)mma_stage<F_IN, HD, 0>,
                         cudaFuncAttributeMaxDynamicSharedMemorySize, SM12);
    cudaFuncSetAttribute((const void*)mma_stage<HD, HD, 0>,
                         cudaFuncAttributeMaxDynamicSharedMemorySize, SM12);
    cudaFuncSetAttribute((const void*)mma_stage<HD, WD, 1>,
                         cudaFuncAttributeMaxDynamicSharedMemorySize, SM3);

    // out = bh (also clears the 0xAA poison)
    init_out<<<1, 32>>>(out, bh);

    // splits: X and weights -> bf16 hi/lo (weights transposed to [N,K])
    convert_X<<<(NROWS * F_IN) / (256 * 4), 256>>>(X, xh, xl);
    convert_weights<<<(F_IN * HD) / 256, 256>>>(W1, W2, Wq,
                                                w1h, w1l, w2h, w2l, wqh, wql);

    // h1 = relu(X @ W1 + b1)
    mma_stage<F_IN, HD, 0><<<NROWS / 64, 256, SM12>>>(
        xh, xl, w1h, w1l, b1, h1h, h1l, nullptr, nullptr);

    // h2 = relu(h1 @ W2 + b2)
    mma_stage<HD, HD, 0><<<NROWS / 64, 256, SM12>>>(
        h1h, h1l, w2h, w2l, b2, h2h, h2l, nullptr, nullptr);

    // out += sum(tanh(h2 @ Wq + bq) * Wh)
    mma_stage<HD, WD, 1><<<NROWS / 64, 256, SM3>>>(
        h2h, h2l, wqh, wql, bq, nullptr, nullptr, Wh, out);
}